// round 6
// baseline (speedup 1.0000x reference)
#include <cuda_runtime.h>
#include <cstdint>

// GlobalFilter: y = irfft(rfft(x, axis=-1) * w, n=10, axis=-1)
// x: [B, DIM, 10] f32, w: [DIM, 6, 2] f32 -> y: [B, DIM, 10] f32
// R6: persistent blocks; reads = cp.async.cg depth-2 prefetch over 4 buffers;
// writes = single cp.async.bulk (20KB) shared->global per tile.

#define THREADS 256
#define TILE_ROWS 512
#define NPTS 10
#define TILE_ELEMS (TILE_ROWS * NPTS)     // 5120 floats = 20480 B
#define TILE_V4 (TILE_ELEMS / 4)          // 1280 float4 -> 5 per thread
#define TILE_BYTES (TILE_ELEMS * 4)       // 20480
#define NBUF 4
#define SMEM_BYTES (NBUF * TILE_BYTES)    // 81920

__host__ __device__ constexpr float ctC(int j) {
    const float t[10] = {1.0f, 0.80901699437494745f, 0.30901699437494745f,
                         -0.30901699437494745f, -0.80901699437494745f, -1.0f,
                         -0.80901699437494745f, -0.30901699437494745f,
                         0.30901699437494745f, 0.80901699437494745f};
    return t[j % 10];
}
__host__ __device__ constexpr float ctS(int j) {
    const float t[10] = {0.0f, 0.58778525229247314f, 0.95105651629515353f,
                         0.95105651629515353f, 0.58778525229247314f, 0.0f,
                         -0.58778525229247314f, -0.95105651629515353f,
                         -0.95105651629515353f, -0.58778525229247314f};
    return t[j % 10];
}

__device__ __forceinline__ void cp_async16(uint32_t saddr, const void* gptr) {
    asm volatile("cp.async.cg.shared.global [%0], [%1], 16;"
                 :: "r"(saddr), "l"(gptr));
}
#define CPA_COMMIT() asm volatile("cp.async.commit_group;" ::: "memory")
#define CPA_WAIT1()  asm volatile("cp.async.wait_group 1;" ::: "memory")

__device__ __forceinline__ void bulk_store(const void* gptr, uint32_t saddr,
                                           uint32_t nbytes) {
    asm volatile("cp.async.bulk.global.shared::cta.bulk_group [%0], [%1], %2;"
                 :: "l"(gptr), "r"(saddr), "r"(nbytes) : "memory");
}
#define BULK_COMMIT()     asm volatile("cp.async.bulk.commit_group;" ::: "memory")
#define BULK_WAIT_READ1() asm volatile("cp.async.bulk.wait_group.read 1;" ::: "memory")
#define BULK_WAIT_ALL()   asm volatile("cp.async.bulk.wait_group 0;" ::: "memory")
#define FENCE_ASYNC()     asm volatile("fence.proxy.async.shared::cta;" ::: "memory")

// core 10-point filtered round-trip
__device__ __forceinline__ void dft10(const float xv[NPTS], float yv[NPTS],
                                      float4 w0, float4 w1, float4 w2)
{
    float u[5], v[5];
    #pragma unroll
    for (int s = 0; s < 5; ++s) {
        u[s] = xv[s] + xv[s + 5];
        v[s] = xv[s] - xv[s + 5];
    }
    float Xr0 = u[0] + u[1] + u[2] + u[3] + u[4];
    float Xr2 = u[0], Xi2 = 0.f, Xr4 = u[0], Xi4 = 0.f;
    #pragma unroll
    for (int s = 1; s < 5; ++s) {
        Xr2 += ctC(2 * s) * u[s];  Xi2 -= ctS(2 * s) * u[s];
        Xr4 += ctC(4 * s) * u[s];  Xi4 -= ctS(4 * s) * u[s];
    }
    float Xr1 = v[0], Xi1 = 0.f, Xr3 = v[0], Xi3 = 0.f;
    #pragma unroll
    for (int s = 1; s < 5; ++s) {
        Xr1 += ctC(1 * s) * v[s];  Xi1 -= ctS(1 * s) * v[s];
        Xr3 += ctC(3 * s) * v[s];  Xi3 -= ctS(3 * s) * v[s];
    }
    float Xr5 = v[0] - v[1] + v[2] - v[3] + v[4];

    const float a1 = w0.z, b1 = w0.w;
    const float a2 = w1.x, b2 = w1.y;
    const float a3 = w1.z, b3 = w1.w;
    const float a4 = w2.x, b4 = w2.y;
    const float Zr0 = 0.1f * (Xr0 * w0.x);
    const float Zr5 = 0.1f * (Xr5 * w2.z);
    const float zr1 = 0.2f * (Xr1 * a1 - Xi1 * b1);
    const float zi1 = 0.2f * (Xr1 * b1 + Xi1 * a1);
    const float zr2 = 0.2f * (Xr2 * a2 - Xi2 * b2);
    const float zi2 = 0.2f * (Xr2 * b2 + Xi2 * a2);
    const float zr3 = 0.2f * (Xr3 * a3 - Xi3 * b3);
    const float zi3 = 0.2f * (Xr3 * b3 + Xi3 * a3);
    const float zr4 = 0.2f * (Xr4 * a4 - Xi4 * b4);
    const float zi4 = 0.2f * (Xr4 * b4 + Xi4 * a4);

    #pragma unroll
    for (int t = 0; t < 5; ++t) {
        float E = Zr0
                + zr2 * ctC(2 * t) - zi2 * ctS(2 * t)
                + zr4 * ctC(4 * t) - zi4 * ctS(4 * t);
        float O = ((t & 1) ? -Zr5 : Zr5)
                + zr1 * ctC(t)     - zi1 * ctS(t)
                + zr3 * ctC(3 * t) - zi3 * ctS(3 * t);
        yv[t]     = E + O;
        yv[t + 5] = E - O;
    }
}

__device__ __forceinline__ void process_row(float* sx, int ridx,
                                            const float* __restrict__ w, int d)
{
    const float4* wp = reinterpret_cast<const float4*>(w + d * 12);
    const float4 w0 = wp[0];
    const float4 w1 = wp[1];
    const float4 w2 = wp[2];

    float xv[NPTS], yv[NPTS];
    const float2* s2 = reinterpret_cast<const float2*>(sx);
    #pragma unroll
    for (int i = 0; i < 5; ++i) {
        float2 p = s2[ridx * 5 + i];
        xv[2 * i] = p.x; xv[2 * i + 1] = p.y;
    }
    dft10(xv, yv, w0, w1, w2);
    float2* s2w = reinterpret_cast<float2*>(sx);
    #pragma unroll
    for (int i = 0; i < 5; ++i) {
        float2 p; p.x = yv[2 * i]; p.y = yv[2 * i + 1];
        s2w[ridx * 5 + i] = p;
    }
}

__global__ __launch_bounds__(THREADS)
void global_filter_kernel(const float* __restrict__ x,
                          const float* __restrict__ w,
                          float* __restrict__ y,
                          int n_rows, int dim, int dim_mask, int ntiles)
{
    extern __shared__ float sx[];   // NBUF * TILE_ELEMS floats

    const int tid    = threadIdx.x;
    const int stride = gridDim.x;
    const int t0     = blockIdx.x;

    uint32_t sbase = (uint32_t)__cvta_generic_to_shared(sx);

    // ---- preamble: prefetch tiles for iterations 0 and 1 ----
    #pragma unroll
    for (int p = 0; p < 2; ++p) {
        const long long tp = (long long)t0 + (long long)p * stride;
        if (tp < ntiles && (tp + 1) * TILE_ROWS <= (long long)n_rows) {
            const float4* g = reinterpret_cast<const float4*>(x) + tp * TILE_V4;
            const uint32_t sb = sbase + (uint32_t)p * TILE_BYTES;
            #pragma unroll
            for (int i = 0; i < 5; ++i)
                cp_async16(sb + (uint32_t)(tid + i * THREADS) * 16u,
                           g + tid + i * THREADS);
        }
        CPA_COMMIT();
    }

    int k = 0;
    for (long long t = t0; t < ntiles; t += stride, ++k) {
        const int s  = k & (NBUF - 1);
        const int sp = (k + 2) & (NBUF - 1);
        float* buf = sx + s * TILE_ELEMS;
        const bool full = (t + 1) * TILE_ROWS <= (long long)n_rows;

        CPA_WAIT1();                 // this iteration's load complete
        if (tid == 0) BULK_WAIT_READ1();  // buf sp's old store: smem fully read
        __syncthreads();

        // ---- prefetch iteration k+2 into buf sp ----
        const long long tn = t + 2LL * stride;
        if (tn < ntiles && (tn + 1) * TILE_ROWS <= (long long)n_rows) {
            const float4* g = reinterpret_cast<const float4*>(x) + tn * TILE_V4;
            const uint32_t sb = sbase + (uint32_t)sp * TILE_BYTES;
            #pragma unroll
            for (int i = 0; i < 5; ++i)
                cp_async16(sb + (uint32_t)(tid + i * THREADS) * 16u,
                           g + tid + i * THREADS);
        }
        CPA_COMMIT();                // unconditional: keep group counts aligned

        if (full) {
            // ---- compute: 2 rows per thread, in place ----
            const int rA = (int)(t * TILE_ROWS) + tid;
            const int rB = rA + THREADS;
            const int dA = (dim_mask >= 0) ? (rA & dim_mask) : (rA % dim);
            const int dB = (dim_mask >= 0) ? (rB & dim_mask) : (rB % dim);
            process_row(buf, tid,           w, dA);
            process_row(buf, tid + THREADS, w, dB);
            __syncthreads();

            // ---- single 20KB bulk store ----
            if (tid == 0) {
                FENCE_ASYNC();       // make all threads' STS visible to async proxy
                bulk_store(y + t * TILE_ELEMS,
                           sbase + (uint32_t)s * TILE_BYTES, TILE_BYTES);
            }
        } else {
            // ---- tail tile: straight from global, scalar ----
            const int rows_here = n_rows - (int)(t * TILE_ROWS);
            for (int rr = tid; rr < rows_here; rr += THREADS) {
                const long long row = t * TILE_ROWS + rr;
                const long long rb = row * NPTS;
                const int d = (dim_mask >= 0) ? ((int)row & dim_mask)
                                              : ((int)(row % dim));
                const float4* wp = reinterpret_cast<const float4*>(w + d * 12);
                float xv[NPTS], yv[NPTS];
                #pragma unroll
                for (int i = 0; i < NPTS; ++i) xv[i] = x[rb + i];
                dft10(xv, yv, wp[0], wp[1], wp[2]);
                #pragma unroll
                for (int i = 0; i < NPTS; ++i) y[rb + i] = yv[i];
            }
            __syncthreads();
        }
        if (tid == 0) BULK_COMMIT(); // unconditional: keep bulk group counts aligned
    }

    // drain outstanding bulk stores before exit
    if (tid == 0) BULK_WAIT_ALL();
}

extern "C" void kernel_launch(void* const* d_in, const int* in_sizes, int n_in,
                              void* d_out, int out_size)
{
    const float* x = (const float*)d_in[0];
    const float* w = (const float*)d_in[1];
    float* y = (float*)d_out;

    const int n_rows = in_sizes[0] / NPTS;       // B * DIM
    const int dim    = in_sizes[1] / 12;         // DIM
    const int dim_mask = ((dim & (dim - 1)) == 0) ? (dim - 1) : -1;
    const int ntiles = (n_rows + TILE_ROWS - 1) / TILE_ROWS;

    static int grid_max = 0;
    if (grid_max == 0) {
        cudaFuncSetAttribute(global_filter_kernel,
                             cudaFuncAttributeMaxDynamicSharedMemorySize,
                             SMEM_BYTES);
        int bps = 0, nsm = 0;
        cudaOccupancyMaxActiveBlocksPerMultiprocessor(
            &bps, global_filter_kernel, THREADS, SMEM_BYTES);
        cudaDeviceGetAttribute(&nsm, cudaDevAttrMultiProcessorCount, 0);
        if (bps <= 0) bps = 2;
        if (nsm <= 0) nsm = 148;
        grid_max = bps * nsm;
    }
    int grid = grid_max < ntiles ? grid_max : ntiles;

    global_filter_kernel<<<grid, THREADS, SMEM_BYTES>>>(
        x, y ? w : w, y, n_rows, dim, dim_mask, ntiles);
}

// round 7
// speedup vs baseline: 1.1026x; 1.1026x over previous
#include <cuda_runtime.h>
#include <cstdint>

// GlobalFilter: y = irfft(rfft(x, axis=-1) * w, n=10, axis=-1)
// x: [B, DIM, 10] f32, w: [DIM, 6, 2] f32 -> y: [B, DIM, 10] f32
// R7: one-shot blocks, 512 rows/block, 2 rows/thread.
// Stage-in via cp.async.cg (no register staging -> high occupancy + MLP=5).
// Stage-out via __stcs streaming stores (evict-first, y never re-read).

#define THREADS 256
#define ROWS_PER_BLOCK 512
#define NPTS 10
#define BLK_ELEMS (ROWS_PER_BLOCK * NPTS)   // 5120 floats = 20480 B
#define BLK_V4 (BLK_ELEMS / 4)              // 1280 float4 -> 5 per thread

__host__ __device__ constexpr float ctC(int j) {
    const float t[10] = {1.0f, 0.80901699437494745f, 0.30901699437494745f,
                         -0.30901699437494745f, -0.80901699437494745f, -1.0f,
                         -0.80901699437494745f, -0.30901699437494745f,
                         0.30901699437494745f, 0.80901699437494745f};
    return t[j % 10];
}
__host__ __device__ constexpr float ctS(int j) {
    const float t[10] = {0.0f, 0.58778525229247314f, 0.95105651629515353f,
                         0.95105651629515353f, 0.58778525229247314f, 0.0f,
                         -0.58778525229247314f, -0.95105651629515353f,
                         -0.95105651629515353f, -0.58778525229247314f};
    return t[j % 10];
}

__device__ __forceinline__ void cp_async16(uint32_t saddr, const void* gptr) {
    asm volatile("cp.async.cg.shared.global [%0], [%1], 16;"
                 :: "r"(saddr), "l"(gptr));
}
#define CPA_COMMIT() asm volatile("cp.async.commit_group;" ::: "memory")
#define CPA_WAIT0()  asm volatile("cp.async.wait_group 0;" ::: "memory")

// core 10-point filtered round-trip: xv -> yv
__device__ __forceinline__ void dft10(const float xv[NPTS], float yv[NPTS],
                                      float4 w0, float4 w1, float4 w2)
{
    float u[5], v[5];
    #pragma unroll
    for (int s = 0; s < 5; ++s) {
        u[s] = xv[s] + xv[s + 5];
        v[s] = xv[s] - xv[s + 5];
    }
    float Xr0 = u[0] + u[1] + u[2] + u[3] + u[4];
    float Xr2 = u[0], Xi2 = 0.f, Xr4 = u[0], Xi4 = 0.f;
    #pragma unroll
    for (int s = 1; s < 5; ++s) {
        Xr2 += ctC(2 * s) * u[s];  Xi2 -= ctS(2 * s) * u[s];
        Xr4 += ctC(4 * s) * u[s];  Xi4 -= ctS(4 * s) * u[s];
    }
    float Xr1 = v[0], Xi1 = 0.f, Xr3 = v[0], Xi3 = 0.f;
    #pragma unroll
    for (int s = 1; s < 5; ++s) {
        Xr1 += ctC(1 * s) * v[s];  Xi1 -= ctS(1 * s) * v[s];
        Xr3 += ctC(3 * s) * v[s];  Xi3 -= ctS(3 * s) * v[s];
    }
    float Xr5 = v[0] - v[1] + v[2] - v[3] + v[4];

    const float a1 = w0.z, b1 = w0.w;
    const float a2 = w1.x, b2 = w1.y;
    const float a3 = w1.z, b3 = w1.w;
    const float a4 = w2.x, b4 = w2.y;
    const float Zr0 = 0.1f * (Xr0 * w0.x);
    const float Zr5 = 0.1f * (Xr5 * w2.z);
    const float zr1 = 0.2f * (Xr1 * a1 - Xi1 * b1);
    const float zi1 = 0.2f * (Xr1 * b1 + Xi1 * a1);
    const float zr2 = 0.2f * (Xr2 * a2 - Xi2 * b2);
    const float zi2 = 0.2f * (Xr2 * b2 + Xi2 * a2);
    const float zr3 = 0.2f * (Xr3 * a3 - Xi3 * b3);
    const float zi3 = 0.2f * (Xr3 * b3 + Xi3 * a3);
    const float zr4 = 0.2f * (Xr4 * a4 - Xi4 * b4);
    const float zi4 = 0.2f * (Xr4 * b4 + Xi4 * a4);

    #pragma unroll
    for (int t = 0; t < 5; ++t) {
        float E = Zr0
                + zr2 * ctC(2 * t) - zi2 * ctS(2 * t)
                + zr4 * ctC(4 * t) - zi4 * ctS(4 * t);
        float O = ((t & 1) ? -Zr5 : Zr5)
                + zr1 * ctC(t)     - zi1 * ctS(t)
                + zr3 * ctC(3 * t) - zi3 * ctS(3 * t);
        yv[t]     = E + O;
        yv[t + 5] = E - O;
    }
}

__device__ __forceinline__ void process_row(float* sx, int ridx,
                                            const float* __restrict__ w, int d)
{
    const float4* wp = reinterpret_cast<const float4*>(w + d * 12);
    const float4 w0 = wp[0];
    const float4 w1 = wp[1];
    const float4 w2 = wp[2];

    float xv[NPTS], yv[NPTS];
    const float2* s2 = reinterpret_cast<const float2*>(sx);
    #pragma unroll
    for (int i = 0; i < 5; ++i) {
        float2 p = s2[ridx * 5 + i];
        xv[2 * i] = p.x; xv[2 * i + 1] = p.y;
    }
    dft10(xv, yv, w0, w1, w2);
    float2* s2w = reinterpret_cast<float2*>(sx);
    #pragma unroll
    for (int i = 0; i < 5; ++i) {
        float2 p; p.x = yv[2 * i]; p.y = yv[2 * i + 1];
        s2w[ridx * 5 + i] = p;
    }
}

__global__ __launch_bounds__(THREADS)
void global_filter_kernel(const float* __restrict__ x,
                          const float* __restrict__ w,
                          float* __restrict__ y,
                          int n_rows, int dim, int dim_mask)
{
    __shared__ float sx[BLK_ELEMS];   // 20480 B

    const int tid  = threadIdx.x;
    const int row0 = blockIdx.x * ROWS_PER_BLOCK;
    const int rows_here = min(ROWS_PER_BLOCK, n_rows - row0);
    const long long base = (long long)row0 * NPTS;

    const uint32_t sbase = (uint32_t)__cvta_generic_to_shared(sx);

    if (rows_here == ROWS_PER_BLOCK) {
        // ---- stage in: 5 cp.async.cg per thread (async proxy holds MLP) ----
        const float4* g = reinterpret_cast<const float4*>(x + base);
        #pragma unroll
        for (int i = 0; i < 5; ++i)
            cp_async16(sbase + (uint32_t)(tid + i * THREADS) * 16u,
                       g + tid + i * THREADS);
        CPA_COMMIT();
        CPA_WAIT0();
        __syncthreads();

        // ---- compute: 2 rows per thread, in place ----
        const int rA = row0 + tid;
        const int rB = rA + THREADS;
        const int dA = (dim_mask >= 0) ? (rA & dim_mask) : (rA % dim);
        const int dB = (dim_mask >= 0) ? (rB & dim_mask) : (rB % dim);
        process_row(sx, tid,           w, dA);
        process_row(sx, tid + THREADS, w, dB);
        __syncthreads();

        // ---- stage out: streaming (evict-first) float4 stores ----
        float4* gy = reinterpret_cast<float4*>(y + base);
        const float4* s4 = reinterpret_cast<const float4*>(sx);
        #pragma unroll
        for (int i = 0; i < 5; ++i)
            __stcs(gy + tid + i * THREADS, s4[tid + i * THREADS]);
    } else {
        // ---- tail block: straight from global, scalar ----
        for (int rr = tid; rr < rows_here; rr += THREADS) {
            const int row = row0 + rr;
            const long long rb = (long long)row * NPTS;
            const int d = (dim_mask >= 0) ? (row & dim_mask) : (row % dim);
            const float4* wp = reinterpret_cast<const float4*>(w + d * 12);
            float xv[NPTS], yv[NPTS];
            #pragma unroll
            for (int i = 0; i < NPTS; ++i) xv[i] = x[rb + i];
            dft10(xv, yv, wp[0], wp[1], wp[2]);
            #pragma unroll
            for (int i = 0; i < NPTS; ++i) y[rb + i] = yv[i];
        }
    }
}

extern "C" void kernel_launch(void* const* d_in, const int* in_sizes, int n_in,
                              void* d_out, int out_size)
{
    const float* x = (const float*)d_in[0];
    const float* w = (const float*)d_in[1];
    float* y = (float*)d_out;

    const int n_rows = in_sizes[0] / NPTS;       // B * DIM
    const int dim    = in_sizes[1] / 12;         // DIM
    const int dim_mask = ((dim & (dim - 1)) == 0) ? (dim - 1) : -1;

    const int blocks = (n_rows + ROWS_PER_BLOCK - 1) / ROWS_PER_BLOCK;
    global_filter_kernel<<<blocks, THREADS>>>(x, w, y, n_rows, dim, dim_mask);
}

// round 8
// speedup vs baseline: 1.1500x; 1.0430x over previous
#include <cuda_runtime.h>
#include <cstdint>

// GlobalFilter: y = irfft(rfft(x, axis=-1) * w, n=10, axis=-1)
// x: [B, DIM, 10] f32, w: [DIM, 6, 2] f32 -> y: [B, DIM, 10] f32
// R8: warp-autonomous sub-tiles. Each warp owns 64 rows (2560 B):
// cp.async stage-in -> syncwarp -> compute (2 rows/lane) -> syncwarp ->
// __stcs stage-out. NO block barriers: warps de-phase, so reads and
// writes interleave smoothly at the DRAM controller instead of flipping
// direction in block-synchronized bursts.

#define THREADS 256
#define WARPS 8
#define WARP_ROWS 64
#define ROWS_PER_BLOCK (WARPS * WARP_ROWS)   // 512
#define NPTS 10
#define WARP_ELEMS (WARP_ROWS * NPTS)        // 640 floats = 2560 B
#define WARP_V4 (WARP_ELEMS / 4)             // 160 float4 -> 5 per lane

__host__ __device__ constexpr float ctC(int j) {
    const float t[10] = {1.0f, 0.80901699437494745f, 0.30901699437494745f,
                         -0.30901699437494745f, -0.80901699437494745f, -1.0f,
                         -0.80901699437494745f, -0.30901699437494745f,
                         0.30901699437494745f, 0.80901699437494745f};
    return t[j % 10];
}
__host__ __device__ constexpr float ctS(int j) {
    const float t[10] = {0.0f, 0.58778525229247314f, 0.95105651629515353f,
                         0.95105651629515353f, 0.58778525229247314f, 0.0f,
                         -0.58778525229247314f, -0.95105651629515353f,
                         -0.95105651629515353f, -0.58778525229247314f};
    return t[j % 10];
}

__device__ __forceinline__ void cp_async16(uint32_t saddr, const void* gptr) {
    asm volatile("cp.async.cg.shared.global [%0], [%1], 16;"
                 :: "r"(saddr), "l"(gptr));
}
#define CPA_COMMIT() asm volatile("cp.async.commit_group;" ::: "memory")
#define CPA_WAIT0()  asm volatile("cp.async.wait_group 0;" ::: "memory")

// core 10-point filtered round-trip: xv -> yv
__device__ __forceinline__ void dft10(const float xv[NPTS], float yv[NPTS],
                                      float4 w0, float4 w1, float4 w2)
{
    float u[5], v[5];
    #pragma unroll
    for (int s = 0; s < 5; ++s) {
        u[s] = xv[s] + xv[s + 5];
        v[s] = xv[s] - xv[s + 5];
    }
    float Xr0 = u[0] + u[1] + u[2] + u[3] + u[4];
    float Xr2 = u[0], Xi2 = 0.f, Xr4 = u[0], Xi4 = 0.f;
    #pragma unroll
    for (int s = 1; s < 5; ++s) {
        Xr2 += ctC(2 * s) * u[s];  Xi2 -= ctS(2 * s) * u[s];
        Xr4 += ctC(4 * s) * u[s];  Xi4 -= ctS(4 * s) * u[s];
    }
    float Xr1 = v[0], Xi1 = 0.f, Xr3 = v[0], Xi3 = 0.f;
    #pragma unroll
    for (int s = 1; s < 5; ++s) {
        Xr1 += ctC(1 * s) * v[s];  Xi1 -= ctS(1 * s) * v[s];
        Xr3 += ctC(3 * s) * v[s];  Xi3 -= ctS(3 * s) * v[s];
    }
    float Xr5 = v[0] - v[1] + v[2] - v[3] + v[4];

    const float a1 = w0.z, b1 = w0.w;
    const float a2 = w1.x, b2 = w1.y;
    const float a3 = w1.z, b3 = w1.w;
    const float a4 = w2.x, b4 = w2.y;
    const float Zr0 = 0.1f * (Xr0 * w0.x);
    const float Zr5 = 0.1f * (Xr5 * w2.z);
    const float zr1 = 0.2f * (Xr1 * a1 - Xi1 * b1);
    const float zi1 = 0.2f * (Xr1 * b1 + Xi1 * a1);
    const float zr2 = 0.2f * (Xr2 * a2 - Xi2 * b2);
    const float zi2 = 0.2f * (Xr2 * b2 + Xi2 * a2);
    const float zr3 = 0.2f * (Xr3 * a3 - Xi3 * b3);
    const float zi3 = 0.2f * (Xr3 * b3 + Xi3 * a3);
    const float zr4 = 0.2f * (Xr4 * a4 - Xi4 * b4);
    const float zi4 = 0.2f * (Xr4 * b4 + Xi4 * a4);

    #pragma unroll
    for (int t = 0; t < 5; ++t) {
        float E = Zr0
                + zr2 * ctC(2 * t) - zi2 * ctS(2 * t)
                + zr4 * ctC(4 * t) - zi4 * ctS(4 * t);
        float O = ((t & 1) ? -Zr5 : Zr5)
                + zr1 * ctC(t)     - zi1 * ctS(t)
                + zr3 * ctC(3 * t) - zi3 * ctS(3 * t);
        yv[t]     = E + O;
        yv[t + 5] = E - O;
    }
}

// process one row stored at sx[ridx*10 .. ridx*10+10)
__device__ __forceinline__ void process_row(float* sx, int ridx,
                                            const float* __restrict__ w, int d)
{
    const float4* wp = reinterpret_cast<const float4*>(w + d * 12);
    const float4 w0 = wp[0];
    const float4 w1 = wp[1];
    const float4 w2 = wp[2];

    float xv[NPTS], yv[NPTS];
    const float2* s2 = reinterpret_cast<const float2*>(sx);
    #pragma unroll
    for (int i = 0; i < 5; ++i) {
        float2 p = s2[ridx * 5 + i];
        xv[2 * i] = p.x; xv[2 * i + 1] = p.y;
    }
    dft10(xv, yv, w0, w1, w2);
    float2* s2w = reinterpret_cast<float2*>(sx);
    #pragma unroll
    for (int i = 0; i < 5; ++i) {
        float2 p; p.x = yv[2 * i]; p.y = yv[2 * i + 1];
        s2w[ridx * 5 + i] = p;
    }
}

__global__ __launch_bounds__(THREADS)
void global_filter_kernel(const float* __restrict__ x,
                          const float* __restrict__ w,
                          float* __restrict__ y,
                          int n_rows, int dim, int dim_mask)
{
    __shared__ float sx[ROWS_PER_BLOCK * NPTS];   // 20480 B

    const int tid  = threadIdx.x;
    const int wid  = tid >> 5;
    const int lane = tid & 31;
    const int row0 = blockIdx.x * ROWS_PER_BLOCK;
    const int rows_here = min(ROWS_PER_BLOCK, n_rows - row0);

    if (rows_here == ROWS_PER_BLOCK) {
        // ---- warp-autonomous path: no block barriers ----
        const int wrow0 = row0 + wid * WARP_ROWS;        // warp's first row
        float* ws = sx + wid * WARP_ELEMS;               // warp's smem region
        const uint32_t wsb = (uint32_t)__cvta_generic_to_shared(ws);

        // stage in: 5 cp.async per lane (warp covers 160 float4 = 2560 B)
        const float4* g = reinterpret_cast<const float4*>(x) +
                          (long long)wrow0 * NPTS / 4;
        #pragma unroll
        for (int i = 0; i < 5; ++i)
            cp_async16(wsb + (uint32_t)(lane + i * 32) * 16u,
                       g + lane + i * 32);
        CPA_COMMIT();
        CPA_WAIT0();
        __syncwarp();

        // compute: 2 rows per lane (rows lane and lane+32 within warp tile)
        const int rA = wrow0 + lane;
        const int rB = rA + 32;
        const int dA = (dim_mask >= 0) ? (rA & dim_mask) : (rA % dim);
        const int dB = (dim_mask >= 0) ? (rB & dim_mask) : (rB % dim);
        process_row(ws, lane,      w, dA);
        process_row(ws, lane + 32, w, dB);
        __syncwarp();

        // stage out: streaming float4 stores
        float4* gy = reinterpret_cast<float4*>(y) +
                     (long long)wrow0 * NPTS / 4;
        const float4* s4 = reinterpret_cast<const float4*>(ws);
        #pragma unroll
        for (int i = 0; i < 5; ++i)
            __stcs(gy + lane + i * 32, s4[lane + i * 32]);
    } else {
        // ---- tail block: straight from global, scalar ----
        for (int rr = tid; rr < rows_here; rr += THREADS) {
            const int row = row0 + rr;
            const long long rb = (long long)row * NPTS;
            const int d = (dim_mask >= 0) ? (row & dim_mask) : (row % dim);
            const float4* wp = reinterpret_cast<const float4*>(w + d * 12);
            float xv[NPTS], yv[NPTS];
            #pragma unroll
            for (int i = 0; i < NPTS; ++i) xv[i] = x[rb + i];
            dft10(xv, yv, wp[0], wp[1], wp[2]);
            #pragma unroll
            for (int i = 0; i < NPTS; ++i) y[rb + i] = yv[i];
        }
    }
}

extern "C" void kernel_launch(void* const* d_in, const int* in_sizes, int n_in,
                              void* d_out, int out_size)
{
    const float* x = (const float*)d_in[0];
    const float* w = (const float*)d_in[1];
    float* y = (float*)d_out;

    const int n_rows = in_sizes[0] / NPTS;       // B * DIM
    const int dim    = in_sizes[1] / 12;         // DIM
    const int dim_mask = ((dim & (dim - 1)) == 0) ? (dim - 1) : -1;

    const int blocks = (n_rows + ROWS_PER_BLOCK - 1) / ROWS_PER_BLOCK;
    global_filter_kernel<<<blocks, THREADS>>>(x, w, y, n_rows, dim, dim_mask);
}